// round 12
// baseline (speedup 1.0000x reference)
#include <cuda_runtime.h>
#include <cuda_bf16.h>
#include <cstdint>

// Problem constants (B=8, N=4096, D=512, K=8192)
#define D_DIM      512
#define NUM_CODES  8192
#define NUM_QUERY  32768

// FP8 GEMM tiling: CTA 128x128, 8 warps in 2(M) x 4(N), warp tile 64x32, k-chunk 128 fp8
#define CTA_M   128
#define CTA_N   128
#define KC      128                    // fp8 elements per chunk = 128B row (SW granule x8)
#define NTILES  (NUM_CODES / CTA_N)    // 64
#define KSLABS  (D_DIM / KC)           // 4
#define CHUNKS  (NTILES * KSLABS)      // 256
#define THREADS 256
#define STAGES  3
#define NEG_INF (-3.402823466e+38f)

// ---- dynamic smem layout ----
// stage s: A [128 x 128B fp8, swizzled] @ s*32768, B @ s*32768+16384
// cand lists: per (warp_n, row) top-4: float v[4][128][4], int i[4][128][4]
#define STG_BYTES 32768
#define SM_CANDV  (STAGES * STG_BYTES)            // 98304
#define SM_CANDI  (SM_CANDV + 8192)
#define SMEM_TOTAL (SM_CANDV + 16384)             // 114688 B -> 2 CTAs/SM (229376 <= 228KB+carve)

// ---- device scratch (no cudaMalloc allowed) ----
__device__ uint8_t g_x8[(size_t)NUM_QUERY * D_DIM];   // 16MB fp8 e4m3
__device__ uint8_t g_c8[(size_t)NUM_CODES * D_DIM];   //  4MB fp8 e4m3
__device__ float g_cnorm[NUM_CODES];
__device__ int   g_cand[NUM_QUERY * 8];               // top-8 candidates per query

// ============================ PTX helpers (sm_89-level, PTX-portable) ============
__device__ __forceinline__ uint32_t smem_u32(const void* p) {
    uint32_t a;
    asm("{ .reg .u64 t; cvta.to.shared.u64 t, %1; cvt.u32.u64 %0, t; }" : "=r"(a) : "l"(p));
    return a;
}
#define CP_ASYNC16(dst, src) \
    asm volatile("cp.async.cg.shared.global [%0], [%1], 16;" :: "r"(dst), "l"(src))
#define CP_COMMIT() asm volatile("cp.async.commit_group;")
#define LDMATRIX_X4(r, addr) \
    asm volatile("ldmatrix.sync.aligned.m8n8.x4.shared.b16 {%0,%1,%2,%3}, [%4];" \
        : "=r"((r)[0]), "=r"((r)[1]), "=r"((r)[2]), "=r"((r)[3]) : "r"(addr))
// FP8 e4m3 MMA: m16n8k32, fragments byte-compatible with b16 ldmatrix tiles
#define MMA_FP8(d, a, b) \
    asm volatile("mma.sync.aligned.m16n8k32.row.col.f32.e4m3.e4m3.f32 " \
        "{%0,%1,%2,%3}, {%4,%5,%6,%7}, {%8,%9}, {%0,%1,%2,%3};" \
        : "+f"((d)[0]), "+f"((d)[1]), "+f"((d)[2]), "+f"((d)[3]) \
        : "r"((a)[0]), "r"((a)[1]), "r"((a)[2]), "r"((a)[3]), "r"((b)[0]), "r"((b)[1]))

// lexicographic "better score": higher value; tie -> lower index (jnp.argmin first-hit)
__device__ __forceinline__ bool better(float v, int i, float w, int j) {
    return (v > w) || (v == w && i < j);
}

// ============================ small kernels ============================
// fp32 -> e4m3 quantize (values ~N(0,1): well inside e4m3 range, no scale needed)
__global__ void __launch_bounds__(256) quant_kernel(const float* __restrict__ src,
                                                    uint8_t* __restrict__ dst, int n4) {
    int i = blockIdx.x * 256 + threadIdx.x;
    if (i >= n4) return;
    float4 v = reinterpret_cast<const float4*>(src)[i];
    uint16_t p01, p23;
    asm("cvt.rn.satfinite.e4m3x2.f32 %0, %1, %2;" : "=h"(p01) : "f"(v.y), "f"(v.x));
    asm("cvt.rn.satfinite.e4m3x2.f32 %0, %1, %2;" : "=h"(p23) : "f"(v.w), "f"(v.z));
    reinterpret_cast<uint32_t*>(dst)[i] = (uint32_t)p01 | ((uint32_t)p23 << 16);
}

__global__ void __launch_bounds__(128) cnorm_kernel(const float* __restrict__ cb) {
    const int code = blockIdx.x;
    const float4 v = reinterpret_cast<const float4*>(cb + (size_t)code * D_DIM)[threadIdx.x];
    float s = v.x * v.x + v.y * v.y + v.z * v.z + v.w * v.w;
#pragma unroll
    for (int off = 16; off > 0; off >>= 1) s += __shfl_xor_sync(0xffffffffu, s, off);
    __shared__ float ws[4];
    if ((threadIdx.x & 31) == 0) ws[threadIdx.x >> 5] = s;
    __syncthreads();
    if (threadIdx.x == 0) g_cnorm[code] = ws[0] + ws[1] + ws[2] + ws[3];
}

// exact fp32 rescore of 8 candidates per query; one warp per query
__global__ void __launch_bounds__(256) rescore_kernel(const float* __restrict__ X,
    const float* __restrict__ CB, const int* __restrict__ cand, float* __restrict__ out) {
    const int q = blockIdx.x * 8 + (threadIdx.x >> 5);
    const int lane = threadIdx.x & 31;
    int idx[8];
#pragma unroll
    for (int k = 0; k < 8; k++) idx[k] = cand[q * 8 + k];
    float d[8];
#pragma unroll
    for (int k = 0; k < 8; k++) d[k] = 0.f;
    const float4* xr = reinterpret_cast<const float4*>(X + (size_t)q * D_DIM);
#pragma unroll
    for (int p = 0; p < 4; p++) {
        const float4 xv = xr[lane + 32 * p];
#pragma unroll
        for (int k = 0; k < 8; k++) {
            const float4 cv = reinterpret_cast<const float4*>(CB + (size_t)idx[k] * D_DIM)[lane + 32 * p];
            float t;
            t = xv.x - cv.x; d[k] = fmaf(t, t, d[k]);
            t = xv.y - cv.y; d[k] = fmaf(t, t, d[k]);
            t = xv.z - cv.z; d[k] = fmaf(t, t, d[k]);
            t = xv.w - cv.w; d[k] = fmaf(t, t, d[k]);
        }
    }
#pragma unroll
    for (int k = 0; k < 8; k++)
#pragma unroll
        for (int o = 16; o > 0; o >>= 1) d[k] += __shfl_xor_sync(0xffffffffu, d[k], o);
    if (lane == 0) {
        float bd = d[0]; int bi = idx[0];
#pragma unroll
        for (int k = 1; k < 8; k++)
            if (d[k] < bd || (d[k] == bd && idx[k] < bi)) { bd = d[k]; bi = idx[k]; }
        out[q] = (float)bi;
    }
}

// ============================ main fused GEMM+argtop kernel ============================
__device__ __forceinline__ void insert4(float* V, int* I, float v, int ix) {
    if (better(v, ix, V[0], I[0])) {
        V[3]=V[2]; I[3]=I[2]; V[2]=V[1]; I[2]=I[1]; V[1]=V[0]; I[1]=I[0]; V[0]=v; I[0]=ix;
    } else if (better(v, ix, V[1], I[1])) {
        V[3]=V[2]; I[3]=I[2]; V[2]=V[1]; I[2]=I[1]; V[1]=v; I[1]=ix;
    } else if (better(v, ix, V[2], I[2])) {
        V[3]=V[2]; I[3]=I[2]; V[2]=v; I[2]=ix;
    } else if (better(v, ix, V[3], I[3])) {
        V[3]=v; I[3]=ix;
    }
}

__global__ void __launch_bounds__(THREADS, 2) vq_main(
    const uint8_t* __restrict__ X8,
    const uint8_t* __restrict__ C8,
    const float* __restrict__ cnorm,
    int* __restrict__ cand)
{
    extern __shared__ char smem[];
    const uint32_t sbase = smem_u32(smem);
    const int tid = threadIdx.x, lane = tid & 31, wid = tid >> 5;
    const int warp_m = wid >> 2, warp_n = wid & 3;      // 2 x 4 warp grid
    const int rowBase = blockIdx.x * CTA_M;

    float* cv = reinterpret_cast<float*>(smem + SM_CANDV);
    int*   ci = reinterpret_cast<int*>(smem + SM_CANDI);
    for (int i = tid; i < 4 * 128 * 4; i += THREADS) { cv[i] = NEG_INF; ci[i] = 0; }
    __syncthreads();

    // ---- per-thread loader constants (bytes; fp8 row = 512B global, 128B smem) ----
    uint32_t relOff[4], swOff[4];
#pragma unroll
    for (int j = 0; j < 4; j++) {
        const int g = tid + j * THREADS;      // 0..1023 granules of 16B
        const int r = g >> 3, c = g & 7;
        relOff[j] = (uint32_t)(r * D_DIM + c * 16);                 // bytes in global
        swOff[j]  = (uint32_t)(r * 128 + ((c ^ (r & 7)) << 4));     // bytes in smem
    }
    const uint32_t aGlobBase = (uint32_t)rowBase * D_DIM;

    // issue chunk's A+B slab into its stage (8 cp.async.16 per thread)
    auto issue = [&](int cnt) {
        const uint32_t k0 = (uint32_t)(cnt & 3) * KC;               // byte offset along K
        const uint32_t offA = aGlobBase + k0;
        const uint32_t offB = (uint32_t)(cnt >> 2) * (CTA_N * D_DIM) + k0;
        const uint32_t sA = sbase + (uint32_t)(cnt % STAGES) * STG_BYTES;
        const uint32_t sB = sA + 16384;
#pragma unroll
        for (int j = 0; j < 4; j++) {
            CP_ASYNC16(sA + swOff[j], X8 + offA + relOff[j]);
            CP_ASYNC16(sB + swOff[j], C8 + offB + relOff[j]);
        }
    };

    // ---- per-warp ldmatrix constants (row&7 == lane&7 for both A and B) ----
    const uint32_t xorc  = (uint32_t)(lane & 7) << 4;
    const uint32_t halfA = (uint32_t)(lane >> 4) << 4;
    const uint32_t halfB = (uint32_t)((lane >> 3) & 1) << 4;
    uint32_t aRowB[4], bRowB[2];
#pragma unroll
    for (int mt = 0; mt < 4; mt++)
        aRowB[mt] = (uint32_t)((warp_m * 64 + mt * 16 + (lane & 15)) * 128);
#pragma unroll
    for (int h = 0; h < 2; h++)
        bRowB[h] = (uint32_t)((warp_n * 32 + h * 16 + ((lane >> 4) << 3) + (lane & 7)) * 128) + 16384;

    float acc[4][4][4];
#pragma unroll
    for (int m = 0; m < 4; m++)
#pragma unroll
        for (int n = 0; n < 4; n++)
#pragma unroll
            for (int e = 0; e < 4; e++) acc[m][n][e] = 0.f;

    issue(0); CP_COMMIT();
    issue(1); CP_COMMIT();

    for (int cnt = 0; cnt < CHUNKS; cnt++) {
        if (cnt + 1 < CHUNKS) { asm volatile("cp.async.wait_group 1;"); }
        else                  { asm volatile("cp.async.wait_group 0;"); }
        __syncthreads();

        const uint32_t sS = sbase + (uint32_t)(cnt % STAGES) * STG_BYTES;
#pragma unroll
        for (int kk = 0; kk < 4; kk++) {          // 4 x k32(fp8) steps = K 128
            uint32_t a[4][4], b[4][2];
            const uint32_t colA = (uint32_t)(kk << 5) + halfA;
            const uint32_t colB = (uint32_t)(kk << 5) + halfB;
#pragma unroll
            for (int mt = 0; mt < 4; mt++)
                LDMATRIX_X4(a[mt], sS + aRowB[mt] + (colA ^ xorc));
#pragma unroll
            for (int h = 0; h < 2; h++) {
                uint32_t r4[4];
                LDMATRIX_X4(r4, sS + bRowB[h] + (colB ^ xorc));
                b[2 * h][0] = r4[0]; b[2 * h][1] = r4[1];
                b[2 * h + 1][0] = r4[2]; b[2 * h + 1][1] = r4[3];
            }
#pragma unroll
            for (int mt = 0; mt < 4; mt++)
#pragma unroll
                for (int nt = 0; nt < 4; nt++)
                    MMA_FP8(acc[mt][nt], a[mt], b[nt]);
        }

        // ---- per-N-tile fused epilogue (every 4th chunk) ----
        if ((cnt & 3) == 3) {
            const int ntile = cnt >> 2;
            const int colq = ntile * CTA_N + warp_n * 32 + (lane & 3) * 2;
            float cn0[4], cn1[4];
#pragma unroll
            for (int nt = 0; nt < 4; nt++) { cn0[nt] = __ldg(cnorm + colq + nt * 8); cn1[nt] = __ldg(cnorm + colq + nt * 8 + 1); }

#pragma unroll
            for (int mt = 0; mt < 4; mt++) {
#pragma unroll
                for (int half = 0; half < 2; half++) {
                    const int row = warp_m * 64 + mt * 16 + (lane >> 2) + half * 8;
                    float v1 = NEG_INF, v2 = NEG_INF; int i1 = 0, i2 = 0;
#pragma unroll
                    for (int nt = 0; nt < 4; nt++) {
                        const int c0 = colq + nt * 8;
                        const float s0 = fmaf(2.f, acc[mt][nt][half * 2],     -cn0[nt]);
                        const float s1 = fmaf(2.f, acc[mt][nt][half * 2 + 1], -cn1[nt]);
                        if (better(s0, c0, v1, i1))      { v2 = v1; i2 = i1; v1 = s0; i1 = c0; }
                        else if (better(s0, c0, v2, i2)) { v2 = s0; i2 = c0; }
                        if (better(s1, c0 + 1, v1, i1))      { v2 = v1; i2 = i1; v1 = s1; i1 = c0 + 1; }
                        else if (better(s1, c0 + 1, v2, i2)) { v2 = s1; i2 = c0 + 1; }
                    }
                    // merge top-2 across the 4 lanes of the quad (xor 1, 2)
#pragma unroll
                    for (int off = 1; off <= 2; off <<= 1) {
                        const float u1 = __shfl_xor_sync(0xffffffffu, v1, off);
                        const int   j1 = __shfl_xor_sync(0xffffffffu, i1, off);
                        const float u2 = __shfl_xor_sync(0xffffffffu, v2, off);
                        const int   j2 = __shfl_xor_sync(0xffffffffu, i2, off);
                        if (better(u1, j1, v1, i1))      { v2 = v1; i2 = i1; v1 = u1; i1 = j1; }
                        else if (better(u1, j1, v2, i2)) { v2 = u1; i2 = j1; }
                        if (better(u2, j2, v2, i2)) {
                            if (better(u2, j2, v1, i1)) { v2 = v1; i2 = i1; v1 = u2; i1 = j2; }
                            else                         { v2 = u2; i2 = j2; }
                        }
                    }
                    if ((lane & 3) == 0) {   // quad leader updates (warp_n,row) top-4 list
                        const int base = (warp_n * 128 + row) * 4;
                        insert4(cv + base, ci + base, v1, i1);
                        insert4(cv + base, ci + base, v2, i2);
                    }
                }
            }
#pragma unroll
            for (int m = 0; m < 4; m++)
#pragma unroll
                for (int n = 0; n < 4; n++)
#pragma unroll
                    for (int e = 0; e < 4; e++) acc[m][n][e] = 0.f;
        }

        if (cnt + 2 < CHUNKS) { issue(cnt + 2); CP_COMMIT(); }
    }

    __syncthreads();   // all cand lists visible before cross-warp merge

    // ---- merge 4 quarters x top-4 -> global top-8 candidates per query ----
    if (tid < CTA_M) {
        float bv[8]; int bi[8];
#pragma unroll
        for (int k = 0; k < 8; k++) { bv[k] = NEG_INF; bi[k] = 0; }
#pragma unroll
        for (int w = 0; w < 4; w++)
#pragma unroll
            for (int e = 0; e < 4; e++) {
                const float v = cv[(w * 128 + tid) * 4 + e];
                const int  ix = ci[(w * 128 + tid) * 4 + e];
                // 8-deep ordered insert
                if (better(v, ix, bv[7], bi[7])) {
                    int p = 7;
#pragma unroll
                    for (int k = 6; k >= 0; k--)
                        if (better(v, ix, bv[k], bi[k])) p = k;
#pragma unroll
                    for (int k = 7; k >= 1; k--)
                        if (k > p) { bv[k] = bv[k - 1]; bi[k] = bi[k - 1]; }
                    bv[p] = v; bi[p] = ix;
                }
            }
#pragma unroll
        for (int k = 0; k < 8; k++) cand[(rowBase + tid) * 8 + k] = bi[k];
    }
}

// ============================ entry point ============================
extern "C" void kernel_launch(void* const* d_in, const int* in_sizes, int n_in,
                              void* d_out, int out_size) {
    const float *x, *cb;
    if (in_sizes[0] >= in_sizes[1]) { x = (const float*)d_in[0]; cb = (const float*)d_in[1]; }
    else                            { x = (const float*)d_in[1]; cb = (const float*)d_in[0]; }
    float* out = (float*)d_out;

    void *px8, *pc8, *pcn, *pcd;
    cudaGetSymbolAddress(&px8, g_x8);
    cudaGetSymbolAddress(&pc8, g_c8);
    cudaGetSymbolAddress(&pcn, g_cnorm);
    cudaGetSymbolAddress(&pcd, g_cand);

    cudaFuncSetAttribute(vq_main, cudaFuncAttributeMaxDynamicSharedMemorySize, SMEM_TOTAL);

    quant_kernel<<<(NUM_QUERY * D_DIM / 4 + 255) / 256, 256>>>(x, (uint8_t*)px8, NUM_QUERY * D_DIM / 4);
    quant_kernel<<<(NUM_CODES * D_DIM / 4 + 255) / 256, 256>>>(cb, (uint8_t*)pc8, NUM_CODES * D_DIM / 4);
    cnorm_kernel<<<NUM_CODES, 128>>>(cb);
    vq_main<<<NUM_QUERY / CTA_M, THREADS, SMEM_TOTAL>>>(
        (const uint8_t*)px8, (const uint8_t*)pc8, (const float*)pcn, (int*)pcd);
    rescore_kernel<<<NUM_QUERY / 8, 256>>>(x, cb, (const int*)pcd, out);
}

// round 13
// speedup vs baseline: 1.1030x; 1.1030x over previous
#include <cuda_runtime.h>
#include <cuda_bf16.h>
#include <cstdint>

// Problem constants (B=8, N=4096, D=512, K=8192)
#define D_DIM      512
#define NUM_CODES  8192
#define NUM_QUERY  32768

// GEMM tiling: CTA 128x128, 8 warps in 2(M) x 4(N), warp tile 64x32, k-slab 64
#define CTA_M   128
#define CTA_N   128
#define KC      64
#define NTILES  (NUM_CODES / CTA_N)    // 64
#define KSLABS  (D_DIM / KC)           // 8
#define CHUNKS  (NTILES * KSLABS)      // 512
#define THREADS 256
#define STAGES  3
#define NEG_INF (-3.402823466e+38f)

// ---- dynamic smem layout ----
// stage s (s=0..2): A [128x64 bf16, swizzled] @ s*32768, B @ s*32768+16384
// cand lists: per (warp_n, row) top-3:  float v[4][128][3], int i[4][128][3]
#define STG_BYTES 32768
#define SM_CANDV  (STAGES * STG_BYTES)            // 98304
#define SM_CANDI  (SM_CANDV + 6144)
#define SMEM_TOTAL (SM_CANDV + 12288)             // 110592 B -> 2 CTAs/SM

// ---- device scratch (no cudaMalloc allowed) ----
__device__ __nv_bfloat16 g_xb[(size_t)NUM_QUERY * D_DIM];   // 32MB
__device__ __nv_bfloat16 g_cb[(size_t)NUM_CODES * D_DIM];   //  8MB
__device__ float g_cnorm[NUM_CODES];
__device__ int4  g_cand[NUM_QUERY];

// ============================ PTX helpers (sm_80-level, PTX-portable) ============
__device__ __forceinline__ uint32_t smem_u32(const void* p) {
    uint32_t a;
    asm("{ .reg .u64 t; cvta.to.shared.u64 t, %1; cvt.u32.u64 %0, t; }" : "=r"(a) : "l"(p));
    return a;
}
#define CP_ASYNC16(dst, src) \
    asm volatile("cp.async.cg.shared.global [%0], [%1], 16;" :: "r"(dst), "l"(src))
#define CP_COMMIT() asm volatile("cp.async.commit_group;")
#define LDMATRIX_X4(r, addr) \
    asm volatile("ldmatrix.sync.aligned.m8n8.x4.shared.b16 {%0,%1,%2,%3}, [%4];" \
        : "=r"((r)[0]), "=r"((r)[1]), "=r"((r)[2]), "=r"((r)[3]) : "r"(addr))
#define MMA_BF16(d, a, b) \
    asm volatile("mma.sync.aligned.m16n8k16.row.col.f32.bf16.bf16.f32 " \
        "{%0,%1,%2,%3}, {%4,%5,%6,%7}, {%8,%9}, {%0,%1,%2,%3};" \
        : "+f"((d)[0]), "+f"((d)[1]), "+f"((d)[2]), "+f"((d)[3]) \
        : "r"((a)[0]), "r"((a)[1]), "r"((a)[2]), "r"((a)[3]), "r"((b)[0]), "r"((b)[1]))

// lexicographic "better score": higher value; tie -> lower index (jnp.argmin first-hit)
__device__ __forceinline__ bool better(float v, int i, float w, int j) {
    return (v > w) || (v == w && i < j);
}

// ============================ small kernels ============================
__global__ void __launch_bounds__(256) convert_kernel(const float* __restrict__ src,
                                                      __nv_bfloat16* __restrict__ dst, int n4) {
    int i = blockIdx.x * 256 + threadIdx.x;
    if (i >= n4) return;
    float4 v = reinterpret_cast<const float4*>(src)[i];
    __nv_bfloat162* dp = reinterpret_cast<__nv_bfloat162*>(dst) + 2 * i;
    dp[0] = __halves2bfloat162(__float2bfloat16(v.x), __float2bfloat16(v.y));
    dp[1] = __halves2bfloat162(__float2bfloat16(v.z), __float2bfloat16(v.w));
}

__global__ void __launch_bounds__(128) cnorm_kernel(const float* __restrict__ cb) {
    const int code = blockIdx.x;
    const float4 v = reinterpret_cast<const float4*>(cb + (size_t)code * D_DIM)[threadIdx.x];
    float s = v.x * v.x + v.y * v.y + v.z * v.z + v.w * v.w;
#pragma unroll
    for (int off = 16; off > 0; off >>= 1) s += __shfl_xor_sync(0xffffffffu, s, off);
    __shared__ float ws[4];
    if ((threadIdx.x & 31) == 0) ws[threadIdx.x >> 5] = s;
    __syncthreads();
    if (threadIdx.x == 0) g_cnorm[code] = ws[0] + ws[1] + ws[2] + ws[3];
}

// exact fp32 rescore of 4 candidates per query; one warp per query
__global__ void __launch_bounds__(256) rescore_kernel(const float* __restrict__ X,
    const float* __restrict__ CB, const int4* __restrict__ cand, float* __restrict__ out) {
    const int q = blockIdx.x * 8 + (threadIdx.x >> 5);
    const int lane = threadIdx.x & 31;
    const int4 c4 = cand[q];
    int idx[4] = {c4.x, c4.y, c4.z, c4.w};
    float d[4] = {0.f, 0.f, 0.f, 0.f};
    const float4* xr = reinterpret_cast<const float4*>(X + (size_t)q * D_DIM);
#pragma unroll
    for (int p = 0; p < 4; p++) {
        const float4 xv = xr[lane + 32 * p];
#pragma unroll
        for (int k = 0; k < 4; k++) {
            const float4 cv = reinterpret_cast<const float4*>(CB + (size_t)idx[k] * D_DIM)[lane + 32 * p];
            float t;
            t = xv.x - cv.x; d[k] = fmaf(t, t, d[k]);
            t = xv.y - cv.y; d[k] = fmaf(t, t, d[k]);
            t = xv.z - cv.z; d[k] = fmaf(t, t, d[k]);
            t = xv.w - cv.w; d[k] = fmaf(t, t, d[k]);
        }
    }
#pragma unroll
    for (int k = 0; k < 4; k++)
#pragma unroll
        for (int o = 16; o > 0; o >>= 1) d[k] += __shfl_xor_sync(0xffffffffu, d[k], o);
    if (lane == 0) {
        float bd = d[0]; int bi = idx[0];
#pragma unroll
        for (int k = 1; k < 4; k++)
            if (d[k] < bd || (d[k] == bd && idx[k] < bi)) { bd = d[k]; bi = idx[k]; }
        out[q] = (float)bi;
    }
}

// ============================ main fused GEMM+argtop kernel ============================
__device__ __forceinline__ void insert3(float* V, int* I, float v, int ix) {
    if (better(v, ix, V[0], I[0])) { V[2]=V[1]; I[2]=I[1]; V[1]=V[0]; I[1]=I[0]; V[0]=v; I[0]=ix; }
    else if (better(v, ix, V[1], I[1])) { V[2]=V[1]; I[2]=I[1]; V[1]=v; I[1]=ix; }
    else if (better(v, ix, V[2], I[2])) { V[2]=v; I[2]=ix; }
}

__global__ void __launch_bounds__(THREADS, 2) vq_main(
    const __nv_bfloat16* __restrict__ Xb,
    const __nv_bfloat16* __restrict__ Cb,
    const float* __restrict__ cnorm,
    int4* __restrict__ cand)
{
    extern __shared__ char smem[];
    const uint32_t sbase = smem_u32(smem);
    const int tid = threadIdx.x, lane = tid & 31, wid = tid >> 5;
    const int warp_m = wid >> 2, warp_n = wid & 3;      // 2 x 4 warp grid
    const int rowBase = blockIdx.x * CTA_M;

    float* cv = reinterpret_cast<float*>(smem + SM_CANDV);
    int*   ci = reinterpret_cast<int*>(smem + SM_CANDI);
    for (int i = tid; i < 4 * 128 * 3; i += THREADS) { cv[i] = NEG_INF; ci[i] = 0; }
    __syncthreads();

    const uint32_t aGlobBase = (uint32_t)rowBase * D_DIM;

    // issue chunk's A+B slab into its stage (8 cp.async.16 per thread);
    // offsets recomputed inline (ALU is cheap; registers are the scarce resource)
    auto issue = [&](int cnt) {
        const uint32_t k0 = (uint32_t)(cnt & 7) * KC;
        const uint32_t offA = aGlobBase + k0;
        const uint32_t offB = (uint32_t)(cnt >> 3) * (CTA_N * D_DIM) + k0;
        const uint32_t sA = sbase + (uint32_t)(cnt % STAGES) * STG_BYTES;
        const uint32_t sB = sA + 16384;
#pragma unroll
        for (int j = 0; j < 4; j++) {
            const int g = tid + j * THREADS;      // 0..1023 granules of 16B
            const int r = g >> 3, c = g & 7;
            const uint32_t rel = (uint32_t)(r * D_DIM + c * 8);                // elements
            const uint32_t sw  = (uint32_t)(r * 128 + ((c ^ (r & 7)) << 4));   // bytes
            CP_ASYNC16(sA + sw, Xb + offA + rel);
            CP_ASYNC16(sB + sw, Cb + offB + rel);
        }
    };

    // ---- per-warp ldmatrix constants (row&7 == lane&7 for both A and B rows) ----
    const uint32_t xorc  = (uint32_t)(lane & 7) << 4;
    const uint32_t halfA = (uint32_t)(lane >> 4) << 4;          // k-half select for A
    const uint32_t halfB = (uint32_t)((lane >> 3) & 1) << 4;    // k-half select for B
    uint32_t aRowB[4], bRowB[2];
#pragma unroll
    for (int mt = 0; mt < 4; mt++)
        aRowB[mt] = (uint32_t)((warp_m * 64 + mt * 16 + (lane & 15)) * 128);
#pragma unroll
    for (int h = 0; h < 2; h++)
        bRowB[h] = (uint32_t)((warp_n * 32 + h * 16 + ((lane >> 4) << 3) + (lane & 7)) * 128) + 16384;

    float acc[4][4][4];
#pragma unroll
    for (int m = 0; m < 4; m++)
#pragma unroll
        for (int n = 0; n < 4; n++)
#pragma unroll
            for (int e = 0; e < 4; e++) acc[m][n][e] = 0.f;

    // fragment load / mma helpers (double-buffered software pipeline)
    auto load_frags = [&](uint32_t sS, uint32_t kk, uint32_t (&A)[4][4], uint32_t (&B)[4][2]) {
        const uint32_t colA = (kk << 5) + halfA;
        const uint32_t colB = (kk << 5) + halfB;
#pragma unroll
        for (int mt = 0; mt < 4; mt++)
            LDMATRIX_X4(A[mt], sS + aRowB[mt] + (colA ^ xorc));
#pragma unroll
        for (int h = 0; h < 2; h++) {
            uint32_t r4[4];
            LDMATRIX_X4(r4, sS + bRowB[h] + (colB ^ xorc));
            B[2 * h][0] = r4[0];     B[2 * h][1] = r4[1];
            B[2 * h + 1][0] = r4[2]; B[2 * h + 1][1] = r4[3];
        }
    };
    auto mma_tile = [&](uint32_t (&A)[4][4], uint32_t (&B)[4][2]) {
#pragma unroll
        for (int mt = 0; mt < 4; mt++)
#pragma unroll
            for (int nt = 0; nt < 4; nt++)
                MMA_BF16(acc[mt][nt], A[mt], B[nt]);
    };

    issue(0); CP_COMMIT();
    issue(1); CP_COMMIT();

    uint32_t A0[4][4], B0[4][2], A1[4][4], B1[4][2];

    for (int cnt = 0; cnt < CHUNKS; cnt++) {
        if (cnt + 1 < CHUNKS) { asm volatile("cp.async.wait_group 1;"); }
        else                  { asm volatile("cp.async.wait_group 0;"); }
        __syncthreads();   // chunk `cnt` resident; stage (cnt-1)%3 fully consumed

        const uint32_t sS = sbase + (uint32_t)(cnt % STAGES) * STG_BYTES;
        // pipelined k64 slab: LDSM for kk+1 overlaps MMA group for kk
        load_frags(sS, 0, A0, B0);
        load_frags(sS, 1, A1, B1);
        mma_tile(A0, B0);
        load_frags(sS, 2, A0, B0);
        mma_tile(A1, B1);
        load_frags(sS, 3, A1, B1);
        mma_tile(A0, B0);
        mma_tile(A1, B1);

        // ---- per-N-tile fused epilogue (every 8th chunk) ----
        if ((cnt & 7) == 7) {
            const int ntile = cnt >> 3;
            const int colq = ntile * CTA_N + warp_n * 32 + (lane & 3) * 2;
            float cn0[4], cn1[4];
#pragma unroll
            for (int nt = 0; nt < 4; nt++) { cn0[nt] = __ldg(cnorm + colq + nt * 8); cn1[nt] = __ldg(cnorm + colq + nt * 8 + 1); }

#pragma unroll
            for (int mt = 0; mt < 4; mt++) {
#pragma unroll
                for (int half = 0; half < 2; half++) {
                    const int row = warp_m * 64 + mt * 16 + (lane >> 2) + half * 8;
                    float v1 = NEG_INF, v2 = NEG_INF; int i1 = 0, i2 = 0;
#pragma unroll
                    for (int nt = 0; nt < 4; nt++) {
                        const int c0 = colq + nt * 8;
                        const float s0 = fmaf(2.f, acc[mt][nt][half * 2],     -cn0[nt]);
                        const float s1 = fmaf(2.f, acc[mt][nt][half * 2 + 1], -cn1[nt]);
                        if (better(s0, c0, v1, i1))      { v2 = v1; i2 = i1; v1 = s0; i1 = c0; }
                        else if (better(s0, c0, v2, i2)) { v2 = s0; i2 = c0; }
                        if (better(s1, c0 + 1, v1, i1))      { v2 = v1; i2 = i1; v1 = s1; i1 = c0 + 1; }
                        else if (better(s1, c0 + 1, v2, i2)) { v2 = s1; i2 = c0 + 1; }
                    }
                    // merge top-2 across the 4 lanes of the quad (xor 1, 2)
#pragma unroll
                    for (int off = 1; off <= 2; off <<= 1) {
                        const float u1 = __shfl_xor_sync(0xffffffffu, v1, off);
                        const int   j1 = __shfl_xor_sync(0xffffffffu, i1, off);
                        const float u2 = __shfl_xor_sync(0xffffffffu, v2, off);
                        const int   j2 = __shfl_xor_sync(0xffffffffu, i2, off);
                        if (better(u1, j1, v1, i1))      { v2 = v1; i2 = i1; v1 = u1; i1 = j1; }
                        else if (better(u1, j1, v2, i2)) { v2 = u1; i2 = j1; }
                        if (better(u2, j2, v2, i2)) {
                            if (better(u2, j2, v1, i1)) { v2 = v1; i2 = i1; v1 = u2; i1 = j2; }
                            else                         { v2 = u2; i2 = j2; }
                        }
                    }
                    if ((lane & 3) == 0) {   // quad leader updates (warp_n,row) top-3 list
                        const int base = (warp_n * 128 + row) * 3;
                        insert3(cv + base, ci + base, v1, i1);
                        insert3(cv + base, ci + base, v2, i2);
                    }
                }
            }
#pragma unroll
            for (int m = 0; m < 4; m++)
#pragma unroll
                for (int n = 0; n < 4; n++)
#pragma unroll
                    for (int e = 0; e < 4; e++) acc[m][n][e] = 0.f;
        }

        if (cnt + 2 < CHUNKS) { issue(cnt + 2); CP_COMMIT(); }
    }

    __syncthreads();   // all cand lists visible before cross-warp merge

    // ---- merge 4 quarters x top-3 -> global top-4 candidates per query ----
    if (tid < CTA_M) {
        float bv[4] = {NEG_INF, NEG_INF, NEG_INF, NEG_INF};
        int   bi[4] = {0, 0, 0, 0};
#pragma unroll
        for (int w = 0; w < 4; w++)
#pragma unroll
            for (int e = 0; e < 3; e++) {
                const float v = cv[(w * 128 + tid) * 3 + e];
                const int  ix = ci[(w * 128 + tid) * 3 + e];
                if (better(v, ix, bv[0], bi[0])) {
                    bv[3]=bv[2]; bi[3]=bi[2]; bv[2]=bv[1]; bi[2]=bi[1];
                    bv[1]=bv[0]; bi[1]=bi[0]; bv[0]=v; bi[0]=ix;
                } else if (better(v, ix, bv[1], bi[1])) {
                    bv[3]=bv[2]; bi[3]=bi[2]; bv[2]=bv[1]; bi[2]=bi[1]; bv[1]=v; bi[1]=ix;
                } else if (better(v, ix, bv[2], bi[2])) {
                    bv[3]=bv[2]; bi[3]=bi[2]; bv[2]=v; bi[2]=ix;
                } else if (better(v, ix, bv[3], bi[3])) {
                    bv[3]=v; bi[3]=ix;
                }
            }
        cand[rowBase + tid] = make_int4(bi[0], bi[1], bi[2], bi[3]);
    }
}

// ============================ entry point ============================
extern "C" void kernel_launch(void* const* d_in, const int* in_sizes, int n_in,
                              void* d_out, int out_size) {
    const float *x, *cb;
    if (in_sizes[0] >= in_sizes[1]) { x = (const float*)d_in[0]; cb = (const float*)d_in[1]; }
    else                            { x = (const float*)d_in[1]; cb = (const float*)d_in[0]; }
    float* out = (float*)d_out;

    void *pxb, *pcb, *pcn, *pcd;
    cudaGetSymbolAddress(&pxb, g_xb);
    cudaGetSymbolAddress(&pcb, g_cb);
    cudaGetSymbolAddress(&pcn, g_cnorm);
    cudaGetSymbolAddress(&pcd, g_cand);

    cudaFuncSetAttribute(vq_main, cudaFuncAttributeMaxDynamicSharedMemorySize, SMEM_TOTAL);

    convert_kernel<<<(NUM_QUERY * D_DIM / 4 + 255) / 256, 256>>>(x, (__nv_bfloat16*)pxb, NUM_QUERY * D_DIM / 4);
    convert_kernel<<<(NUM_CODES * D_DIM / 4 + 255) / 256, 256>>>(cb, (__nv_bfloat16*)pcb, NUM_CODES * D_DIM / 4);
    cnorm_kernel<<<NUM_CODES, 128>>>(cb);
    vq_main<<<NUM_QUERY / CTA_M, THREADS, SMEM_TOTAL>>>(
        (const __nv_bfloat16*)pxb, (const __nv_bfloat16*)pcb, (const float*)pcn, (int4*)pcd);
    rescore_kernel<<<NUM_QUERY / 8, 256>>>(x, cb, (const int4*)pcd, out);
}

// round 14
// speedup vs baseline: 1.1656x; 1.0568x over previous
#include <cuda_runtime.h>
#include <cuda_fp16.h>
#include <cstdint>

// Problem constants (B=8, N=4096, D=512, K=8192)
#define D_DIM      512
#define NUM_CODES  8192
#define NUM_QUERY  32768

// GEMM tiling: CTA 128x128, 8 warps in 2(M) x 4(N), warp tile 64x32, k-slab 64
#define CTA_M   128
#define CTA_N   128
#define KC      64
#define NTILES  (NUM_CODES / CTA_N)    // 64
#define KSLABS  (D_DIM / KC)           // 8
#define CHUNKS  (NTILES * KSLABS)      // 512
#define THREADS 256
#define STAGES  3
#define NEG_INF (-3.402823466e+38f)

// ---- dynamic smem layout ----
#define STG_BYTES 32768
#define SM_CANDV  (STAGES * STG_BYTES)            // 98304
#define SM_CANDI  (SM_CANDV + 6144)
#define SMEM_TOTAL (SM_CANDV + 12288)             // 110592 B -> 2 CTAs/SM

// ---- device scratch (no cudaMalloc allowed) ----
__device__ __half g_xh[(size_t)NUM_QUERY * D_DIM];   // 32MB fp16
__device__ __half g_ch[(size_t)NUM_CODES * D_DIM];   //  8MB fp16
__device__ float g_cnorm[NUM_CODES];
__device__ int4  g_cand[NUM_QUERY];

// ============================ PTX helpers (sm_80-level, PTX-portable) ============
__device__ __forceinline__ uint32_t smem_u32(const void* p) {
    uint32_t a;
    asm("{ .reg .u64 t; cvta.to.shared.u64 t, %1; cvt.u32.u64 %0, t; }" : "=r"(a) : "l"(p));
    return a;
}
#define CP_ASYNC16(dst, src) \
    asm volatile("cp.async.cg.shared.global [%0], [%1], 16;" :: "r"(dst), "l"(src))
#define CP_COMMIT() asm volatile("cp.async.commit_group;")
#define LDMATRIX_X4(r, addr) \
    asm volatile("ldmatrix.sync.aligned.m8n8.x4.shared.b16 {%0,%1,%2,%3}, [%4];" \
        : "=r"((r)[0]), "=r"((r)[1]), "=r"((r)[2]), "=r"((r)[3]) : "r"(addr))
// f16 accumulate: 2x HMMA rate vs f32 accumulate on the legacy tensor path
#define MMA_F16ACC(d, a, b) \
    asm volatile("mma.sync.aligned.m16n8k16.row.col.f16.f16.f16.f16 " \
        "{%0,%1}, {%2,%3,%4,%5}, {%6,%7}, {%0,%1};" \
        : "+r"((d)[0]), "+r"((d)[1]) \
        : "r"((a)[0]), "r"((a)[1]), "r"((a)[2]), "r"((a)[3]), "r"((b)[0]), "r"((b)[1]))

// lexicographic "better score": higher value; tie -> lower index (jnp.argmin first-hit)
__device__ __forceinline__ bool better(float v, int i, float w, int j) {
    return (v > w) || (v == w && i < j);
}

// ============================ small kernels ============================
__global__ void __launch_bounds__(256) convert_kernel(const float* __restrict__ src,
                                                      __half* __restrict__ dst, int n4) {
    int i = blockIdx.x * 256 + threadIdx.x;
    if (i >= n4) return;
    float4 v = reinterpret_cast<const float4*>(src)[i];
    __half2* dp = reinterpret_cast<__half2*>(dst) + 2 * i;
    dp[0] = __floats2half2_rn(v.x, v.y);
    dp[1] = __floats2half2_rn(v.z, v.w);
}

__global__ void __launch_bounds__(128) cnorm_kernel(const float* __restrict__ cb) {
    const int code = blockIdx.x;
    const float4 v = reinterpret_cast<const float4*>(cb + (size_t)code * D_DIM)[threadIdx.x];
    float s = v.x * v.x + v.y * v.y + v.z * v.z + v.w * v.w;
#pragma unroll
    for (int off = 16; off > 0; off >>= 1) s += __shfl_xor_sync(0xffffffffu, s, off);
    __shared__ float ws[4];
    if ((threadIdx.x & 31) == 0) ws[threadIdx.x >> 5] = s;
    __syncthreads();
    if (threadIdx.x == 0) g_cnorm[code] = ws[0] + ws[1] + ws[2] + ws[3];
}

// exact fp32 rescore of 4 candidates per query; one warp per query
__global__ void __launch_bounds__(256) rescore_kernel(const float* __restrict__ X,
    const float* __restrict__ CB, const int4* __restrict__ cand, float* __restrict__ out) {
    const int q = blockIdx.x * 8 + (threadIdx.x >> 5);
    const int lane = threadIdx.x & 31;
    const int4 c4 = cand[q];
    int idx[4] = {c4.x, c4.y, c4.z, c4.w};
    float d[4] = {0.f, 0.f, 0.f, 0.f};
    const float4* xr = reinterpret_cast<const float4*>(X + (size_t)q * D_DIM);
#pragma unroll
    for (int p = 0; p < 4; p++) {
        const float4 xv = xr[lane + 32 * p];
#pragma unroll
        for (int k = 0; k < 4; k++) {
            const float4 cv = reinterpret_cast<const float4*>(CB + (size_t)idx[k] * D_DIM)[lane + 32 * p];
            float t;
            t = xv.x - cv.x; d[k] = fmaf(t, t, d[k]);
            t = xv.y - cv.y; d[k] = fmaf(t, t, d[k]);
            t = xv.z - cv.z; d[k] = fmaf(t, t, d[k]);
            t = xv.w - cv.w; d[k] = fmaf(t, t, d[k]);
        }
    }
#pragma unroll
    for (int k = 0; k < 4; k++)
#pragma unroll
        for (int o = 16; o > 0; o >>= 1) d[k] += __shfl_xor_sync(0xffffffffu, d[k], o);
    if (lane == 0) {
        float bd = d[0]; int bi = idx[0];
#pragma unroll
        for (int k = 1; k < 4; k++)
            if (d[k] < bd || (d[k] == bd && idx[k] < bi)) { bd = d[k]; bi = idx[k]; }
        out[q] = (float)bi;
    }
}

// ============================ main fused GEMM+argtop kernel ============================
__device__ __forceinline__ void insert3(float* V, int* I, float v, int ix) {
    if (better(v, ix, V[0], I[0])) { V[2]=V[1]; I[2]=I[1]; V[1]=V[0]; I[1]=I[0]; V[0]=v; I[0]=ix; }
    else if (better(v, ix, V[1], I[1])) { V[2]=V[1]; I[2]=I[1]; V[1]=v; I[1]=ix; }
    else if (better(v, ix, V[2], I[2])) { V[2]=v; I[2]=ix; }
}

__global__ void __launch_bounds__(THREADS, 2) vq_main(
    const __half* __restrict__ Xh,
    const __half* __restrict__ Ch,
    const float* __restrict__ cnorm,
    int4* __restrict__ cand)
{
    extern __shared__ char smem[];
    const uint32_t sbase = smem_u32(smem);
    const int tid = threadIdx.x, lane = tid & 31, wid = tid >> 5;
    const int warp_m = wid >> 2, warp_n = wid & 3;      // 2 x 4 warp grid
    const int rowBase = blockIdx.x * CTA_M;

    float* cv = reinterpret_cast<float*>(smem + SM_CANDV);
    int*   ci = reinterpret_cast<int*>(smem + SM_CANDI);
    for (int i = tid; i < 4 * 128 * 3; i += THREADS) { cv[i] = NEG_INF; ci[i] = 0; }
    __syncthreads();

    const uint32_t aGlobBase = (uint32_t)rowBase * D_DIM;

    // issue chunk's A+B slab into its stage (8 cp.async.16 per thread)
    auto issue = [&](int cnt) {
        const uint32_t k0 = (uint32_t)(cnt & 7) * KC;
        const uint32_t offA = aGlobBase + k0;
        const uint32_t offB = (uint32_t)(cnt >> 3) * (CTA_N * D_DIM) + k0;
        const uint32_t sA = sbase + (uint32_t)(cnt % STAGES) * STG_BYTES;
        const uint32_t sB = sA + 16384;
#pragma unroll
        for (int j = 0; j < 4; j++) {
            const int g = tid + j * THREADS;      // 0..1023 granules of 16B
            const int r = g >> 3, c = g & 7;
            const uint32_t rel = (uint32_t)(r * D_DIM + c * 8);                // elements
            const uint32_t sw  = (uint32_t)(r * 128 + ((c ^ (r & 7)) << 4));   // bytes
            CP_ASYNC16(sA + sw, Xh + offA + rel);
            CP_ASYNC16(sB + sw, Ch + offB + rel);
        }
    };

    // ---- per-warp ldmatrix constants (row&7 == lane&7 for both A and B rows) ----
    const uint32_t xorc  = (uint32_t)(lane & 7) << 4;
    const uint32_t halfA = (uint32_t)(lane >> 4) << 4;          // k-half select for A
    const uint32_t halfB = (uint32_t)((lane >> 3) & 1) << 4;    // k-half select for B
    uint32_t aRowB[4], bRowB[2];
#pragma unroll
    for (int mt = 0; mt < 4; mt++)
        aRowB[mt] = (uint32_t)((warp_m * 64 + mt * 16 + (lane & 15)) * 128);
#pragma unroll
    for (int h = 0; h < 2; h++)
        bRowB[h] = (uint32_t)((warp_n * 32 + h * 16 + ((lane >> 4) << 3) + (lane & 7)) * 128) + 16384;

    // f16x2-packed accumulators: acc[mt][nt][r], r0={c0,c1}, r1={c2,c3}
    uint32_t acc[4][4][2];
#pragma unroll
    for (int m = 0; m < 4; m++)
#pragma unroll
        for (int n = 0; n < 4; n++) { acc[m][n][0] = 0u; acc[m][n][1] = 0u; }

    auto load_frags = [&](uint32_t sS, uint32_t kk, uint32_t (&A)[4][4], uint32_t (&B)[4][2]) {
        const uint32_t colA = (kk << 5) + halfA;
        const uint32_t colB = (kk << 5) + halfB;
#pragma unroll
        for (int mt = 0; mt < 4; mt++)
            LDMATRIX_X4(A[mt], sS + aRowB[mt] + (colA ^ xorc));
#pragma unroll
        for (int h = 0; h < 2; h++) {
            uint32_t r4[4];
            LDMATRIX_X4(r4, sS + bRowB[h] + (colB ^ xorc));
            B[2 * h][0] = r4[0];     B[2 * h][1] = r4[1];
            B[2 * h + 1][0] = r4[2]; B[2 * h + 1][1] = r4[3];
        }
    };
    auto mma_tile = [&](uint32_t (&A)[4][4], uint32_t (&B)[4][2]) {
#pragma unroll
        for (int mt = 0; mt < 4; mt++)
#pragma unroll
            for (int nt = 0; nt < 4; nt++)
                MMA_F16ACC(acc[mt][nt], A[mt], B[nt]);
    };

    issue(0); CP_COMMIT();
    issue(1); CP_COMMIT();

    uint32_t A0[4][4], B0[4][2], A1[4][4], B1[4][2];

    for (int cnt = 0; cnt < CHUNKS; cnt++) {
        if (cnt + 1 < CHUNKS) { asm volatile("cp.async.wait_group 1;"); }
        else                  { asm volatile("cp.async.wait_group 0;"); }
        __syncthreads();   // chunk `cnt` resident; stage (cnt-1)%3 fully consumed

        const uint32_t sS = sbase + (uint32_t)(cnt % STAGES) * STG_BYTES;
        // pipelined k64 slab: LDSM for kk+1 overlaps MMA group for kk
        load_frags(sS, 0, A0, B0);
        load_frags(sS, 1, A1, B1);
        mma_tile(A0, B0);
        load_frags(sS, 2, A0, B0);
        mma_tile(A1, B1);
        load_frags(sS, 3, A1, B1);
        mma_tile(A0, B0);
        mma_tile(A1, B1);

        // ---- per-N-tile fused epilogue (every 8th chunk) ----
        if ((cnt & 7) == 7) {
            const int ntile = cnt >> 3;
            const int colq = ntile * CTA_N + warp_n * 32 + (lane & 3) * 2;
            float cn0[4], cn1[4];
#pragma unroll
            for (int nt = 0; nt < 4; nt++) { cn0[nt] = __ldg(cnorm + colq + nt * 8); cn1[nt] = __ldg(cnorm + colq + nt * 8 + 1); }

#pragma unroll
            for (int mt = 0; mt < 4; mt++) {
#pragma unroll
                for (int half = 0; half < 2; half++) {
                    const int row = warp_m * 64 + mt * 16 + (lane >> 2) + half * 8;
                    float v1 = NEG_INF, v2 = NEG_INF; int i1 = 0, i2 = 0;
#pragma unroll
                    for (int nt = 0; nt < 4; nt++) {
                        const int c0 = colq + nt * 8;
                        const float2 p = __half22float2(
                            *reinterpret_cast<const __half2*>(&acc[mt][nt][half]));
                        const float s0 = fmaf(2.f, p.x, -cn0[nt]);
                        const float s1 = fmaf(2.f, p.y, -cn1[nt]);
                        if (better(s0, c0, v1, i1))      { v2 = v1; i2 = i1; v1 = s0; i1 = c0; }
                        else if (better(s0, c0, v2, i2)) { v2 = s0; i2 = c0; }
                        if (better(s1, c0 + 1, v1, i1))      { v2 = v1; i2 = i1; v1 = s1; i1 = c0 + 1; }
                        else if (better(s1, c0 + 1, v2, i2)) { v2 = s1; i2 = c0 + 1; }
                    }
                    // merge top-2 across the 4 lanes of the quad (xor 1, 2)
#pragma unroll
                    for (int off = 1; off <= 2; off <<= 1) {
                        const float u1 = __shfl_xor_sync(0xffffffffu, v1, off);
                        const int   j1 = __shfl_xor_sync(0xffffffffu, i1, off);
                        const float u2 = __shfl_xor_sync(0xffffffffu, v2, off);
                        const int   j2 = __shfl_xor_sync(0xffffffffu, i2, off);
                        if (better(u1, j1, v1, i1))      { v2 = v1; i2 = i1; v1 = u1; i1 = j1; }
                        else if (better(u1, j1, v2, i2)) { v2 = u1; i2 = j1; }
                        if (better(u2, j2, v2, i2)) {
                            if (better(u2, j2, v1, i1)) { v2 = v1; i2 = i1; v1 = u2; i1 = j2; }
                            else                         { v2 = u2; i2 = j2; }
                        }
                    }
                    if ((lane & 3) == 0) {   // quad leader updates (warp_n,row) top-3 list
                        const int base = (warp_n * 128 + row) * 3;
                        insert3(cv + base, ci + base, v1, i1);
                        insert3(cv + base, ci + base, v2, i2);
                    }
                }
            }
#pragma unroll
            for (int m = 0; m < 4; m++)
#pragma unroll
                for (int n = 0; n < 4; n++) { acc[m][n][0] = 0u; acc[m][n][1] = 0u; }
        }

        if (cnt + 2 < CHUNKS) { issue(cnt + 2); CP_COMMIT(); }
    }

    __syncthreads();   // all cand lists visible before cross-warp merge

    // ---- merge 4 quarters x top-3 -> global top-4 candidates per query ----
    if (tid < CTA_M) {
        float bv[4] = {NEG_INF, NEG_INF, NEG_INF, NEG_INF};
        int   bi[4] = {0, 0, 0, 0};
#pragma unroll
        for (int w = 0; w < 4; w++)
#pragma unroll
            for (int e = 0; e < 3; e++) {
                const float v = cv[(w * 128 + tid) * 3 + e];
                const int  ix = ci[(w * 128 + tid) * 3 + e];
                if (better(v, ix, bv[0], bi[0])) {
                    bv[3]=bv[2]; bi[3]=bi[2]; bv[2]=bv[1]; bi[2]=bi[1];
                    bv[1]=bv[0]; bi[1]=bi[0]; bv[0]=v; bi[0]=ix;
                } else if (better(v, ix, bv[1], bi[1])) {
                    bv[3]=bv[2]; bi[3]=bi[2]; bv[2]=bv[1]; bi[2]=bi[1]; bv[1]=v; bi[1]=ix;
                } else if (better(v, ix, bv[2], bi[2])) {
                    bv[3]=bv[2]; bi[3]=bi[2]; bv[2]=v; bi[2]=ix;
                } else if (better(v, ix, bv[3], bi[3])) {
                    bv[3]=v; bi[3]=ix;
                }
            }
        cand[rowBase + tid] = make_int4(bi[0], bi[1], bi[2], bi[3]);
    }
}

// ============================ entry point ============================
extern "C" void kernel_launch(void* const* d_in, const int* in_sizes, int n_in,
                              void* d_out, int out_size) {
    const float *x, *cb;
    if (in_sizes[0] >= in_sizes[1]) { x = (const float*)d_in[0]; cb = (const float*)d_in[1]; }
    else                            { x = (const float*)d_in[1]; cb = (const float*)d_in[0]; }
    float* out = (float*)d_out;

    void *pxh, *pch, *pcn, *pcd;
    cudaGetSymbolAddress(&pxh, g_xh);
    cudaGetSymbolAddress(&pch, g_ch);
    cudaGetSymbolAddress(&pcn, g_cnorm);
    cudaGetSymbolAddress(&pcd, g_cand);

    cudaFuncSetAttribute(vq_main, cudaFuncAttributeMaxDynamicSharedMemorySize, SMEM_TOTAL);

    convert_kernel<<<(NUM_QUERY * D_DIM / 4 + 255) / 256, 256>>>(x, (__half*)pxh, NUM_QUERY * D_DIM / 4);
    convert_kernel<<<(NUM_CODES * D_DIM / 4 + 255) / 256, 256>>>(cb, (__half*)pch, NUM_CODES * D_DIM / 4);
    cnorm_kernel<<<NUM_CODES, 128>>>(cb);
    vq_main<<<NUM_QUERY / CTA_M, THREADS, SMEM_TOTAL>>>(
        (const __half*)pxh, (const __half*)pch, (const float*)pcn, (int4*)pcd);
    rescore_kernel<<<NUM_QUERY / 8, 256>>>(x, cb, (const int4*)pcd, out);
}

// round 16
// speedup vs baseline: 1.4186x; 1.2170x over previous
#include <cuda_runtime.h>
#include <cuda_fp16.h>
#include <cstdint>

// Problem constants (B=8, N=4096, D=512, K=8192)
#define D_DIM      512
#define NUM_CODES  8192
#define NUM_QUERY  32768

// GEMM tiling: CTA 128x256, 8 warps in 2(M) x 4(N), warp tile 64x64, k-slab 64
#define CTA_M   128
#define CTA_N   256
#define KC      64
#define NTILES  (NUM_CODES / CTA_N)    // 32
#define KSLABS  (D_DIM / KC)           // 8
#define CHUNKS  (NTILES * KSLABS)      // 256
#define THREADS 256
#define STAGES  2
#define NEG_INF (-3.402823466e+38f)

// ---- dynamic smem layout ----
// stage s: A [128x64 f16 swizzled, 16KB] @ s*49152, B [256x64 f16, 32KB] @ +16384
#define STG_BYTES 49152
#define SM_CANDV  (STAGES * STG_BYTES)            // 98304
#define SM_CANDI  (SM_CANDV + 6144)
#define SMEM_TOTAL (SM_CANDV + 12288)             // 110592 B -> 2 CTAs/SM

// ---- device scratch (no cudaMalloc allowed) ----
__device__ __half g_xh[(size_t)NUM_QUERY * D_DIM];   // 32MB fp16
__device__ __half g_ch[(size_t)NUM_CODES * D_DIM];   //  8MB fp16
__device__ float g_cnorm[NUM_CODES];
__device__ int4  g_cand[NUM_QUERY];

// ============================ PTX helpers (sm_80-level, PTX-portable) ============
__device__ __forceinline__ uint32_t smem_u32(const void* p) {
    uint32_t a;
    asm("{ .reg .u64 t; cvta.to.shared.u64 t, %1; cvt.u32.u64 %0, t; }" : "=r"(a) : "l"(p));
    return a;
}
#define CP_ASYNC16(dst, src) \
    asm volatile("cp.async.cg.shared.global [%0], [%1], 16;" :: "r"(dst), "l"(src))
#define CP_COMMIT() asm volatile("cp.async.commit_group;")
#define LDMATRIX_X4(r, addr) \
    asm volatile("ldmatrix.sync.aligned.m8n8.x4.shared.b16 {%0,%1,%2,%3}, [%4];" \
        : "=r"((r)[0]), "=r"((r)[1]), "=r"((r)[2]), "=r"((r)[3]) : "r"(addr))
// f16 accumulate (R14: final codes matched reference exactly on this dataset)
#define MMA_F16ACC(d, a, b) \
    asm volatile("mma.sync.aligned.m16n8k16.row.col.f16.f16.f16.f16 " \
        "{%0,%1}, {%2,%3,%4,%5}, {%6,%7}, {%0,%1};" \
        : "+r"((d)[0]), "+r"((d)[1]) \
        : "r"((a)[0]), "r"((a)[1]), "r"((a)[2]), "r"((a)[3]), "r"((b)[0]), "r"((b)[1]))

// lexicographic "better score": higher value; tie -> lower index (jnp.argmin first-hit)
__device__ __forceinline__ bool better(float v, int i, float w, int j) {
    return (v > w) || (v == w && i < j);
}

// ============================ small kernels ============================
__global__ void __launch_bounds__(256) convert_kernel(const float* __restrict__ src,
                                                      __half* __restrict__ dst, int n4) {
    int i = blockIdx.x * 256 + threadIdx.x;
    if (i >= n4) return;
    float4 v = reinterpret_cast<const float4*>(src)[i];
    __half2* dp = reinterpret_cast<__half2*>(dst) + 2 * i;
    dp[0] = __floats2half2_rn(v.x, v.y);
    dp[1] = __floats2half2_rn(v.z, v.w);
}

__global__ void __launch_bounds__(128) cnorm_kernel(const float* __restrict__ cb) {
    const int code = blockIdx.x;
    const float4 v = reinterpret_cast<const float4*>(cb + (size_t)code * D_DIM)[threadIdx.x];
    float s = v.x * v.x + v.y * v.y + v.z * v.z + v.w * v.w;
#pragma unroll
    for (int off = 16; off > 0; off >>= 1) s += __shfl_xor_sync(0xffffffffu, s, off);
    __shared__ float ws[4];
    if ((threadIdx.x & 31) == 0) ws[threadIdx.x >> 5] = s;
    __syncthreads();
    if (threadIdx.x == 0) g_cnorm[code] = ws[0] + ws[1] + ws[2] + ws[3];
}

// exact fp32 rescore of 4 candidates per query; one warp per query
__global__ void __launch_bounds__(256) rescore_kernel(const float* __restrict__ X,
    const float* __restrict__ CB, const int4* __restrict__ cand, float* __restrict__ out) {
    const int q = blockIdx.x * 8 + (threadIdx.x >> 5);
    const int lane = threadIdx.x & 31;
    const int4 c4 = cand[q];
    int idx[4] = {c4.x, c4.y, c4.z, c4.w};
    float d[4] = {0.f, 0.f, 0.f, 0.f};
    const float4* xr = reinterpret_cast<const float4*>(X + (size_t)q * D_DIM);
#pragma unroll
    for (int p = 0; p < 4; p++) {
        const float4 xv = xr[lane + 32 * p];
#pragma unroll
        for (int k = 0; k < 4; k++) {
            const float4 cv = reinterpret_cast<const float4*>(CB + (size_t)idx[k] * D_DIM)[lane + 32 * p];
            float t;
            t = xv.x - cv.x; d[k] = fmaf(t, t, d[k]);
            t = xv.y - cv.y; d[k] = fmaf(t, t, d[k]);
            t = xv.z - cv.z; d[k] = fmaf(t, t, d[k]);
            t = xv.w - cv.w; d[k] = fmaf(t, t, d[k]);
        }
    }
#pragma unroll
    for (int k = 0; k < 4; k++)
#pragma unroll
        for (int o = 16; o > 0; o >>= 1) d[k] += __shfl_xor_sync(0xffffffffu, d[k], o);
    if (lane == 0) {
        float bd = d[0]; int bi = idx[0];
#pragma unroll
        for (int k = 1; k < 4; k++)
            if (d[k] < bd || (d[k] == bd && idx[k] < bi)) { bd = d[k]; bi = idx[k]; }
        out[q] = (float)bi;
    }
}

// ============================ main fused GEMM+argtop kernel ============================
__device__ __forceinline__ void insert3(float* V, int* I, float v, int ix) {
    if (better(v, ix, V[0], I[0])) { V[2]=V[1]; I[2]=I[1]; V[1]=V[0]; I[1]=I[0]; V[0]=v; I[0]=ix; }
    else if (better(v, ix, V[1], I[1])) { V[2]=V[1]; I[2]=I[1]; V[1]=v; I[1]=ix; }
    else if (better(v, ix, V[2], I[2])) { V[2]=v; I[2]=ix; }
}

__global__ void __launch_bounds__(THREADS, 2) vq_main(
    const __half* __restrict__ Xh,
    const __half* __restrict__ Ch,
    const float* __restrict__ cnorm,
    int4* __restrict__ cand)
{
    extern __shared__ char smem[];
    const uint32_t sbase = smem_u32(smem);
    const int tid = threadIdx.x, lane = tid & 31, wid = tid >> 5;
    const int warp_m = wid >> 2, warp_n = wid & 3;      // 2 x 4 warp grid, warp = 64x64
    const int rowBase = blockIdx.x * CTA_M;

    float* cv = reinterpret_cast<float*>(smem + SM_CANDV);
    int*   ci = reinterpret_cast<int*>(smem + SM_CANDI);
    for (int i = tid; i < 4 * 128 * 3; i += THREADS) { cv[i] = NEG_INF; ci[i] = 0; }
    __syncthreads();

    const uint32_t aGlobBase = (uint32_t)rowBase * D_DIM;

    // issue chunk's A (1024 granules) + B (2048 granules) slab into its stage
    auto issue = [&](int cnt) {
        const uint32_t k0 = (uint32_t)(cnt & 7) * KC;
        const uint32_t offA = aGlobBase + k0;
        const uint32_t offB = (uint32_t)(cnt >> 3) * (CTA_N * D_DIM) + k0;
        const uint32_t sA = sbase + (uint32_t)(cnt % STAGES) * STG_BYTES;
        const uint32_t sB = sA + 16384;
#pragma unroll
        for (int j = 0; j < 4; j++) {          // A: 128 rows x 8 granules
            const int g = tid + j * THREADS;
            const int r = g >> 3, c = g & 7;
            const uint32_t rel = (uint32_t)(r * D_DIM + c * 8);
            const uint32_t sw  = (uint32_t)(r * 128 + ((c ^ (r & 7)) << 4));
            CP_ASYNC16(sA + sw, Xh + offA + rel);
        }
#pragma unroll
        for (int j = 0; j < 8; j++) {          // B: 256 rows x 8 granules
            const int g = tid + j * THREADS;
            const int r = g >> 3, c = g & 7;
            const uint32_t rel = (uint32_t)(r * D_DIM + c * 8);
            const uint32_t sw  = (uint32_t)(r * 128 + ((c ^ (r & 7)) << 4));
            CP_ASYNC16(sB + sw, Ch + offB + rel);
        }
    };

    // ---- per-warp ldmatrix constants (row&7 == lane&7 for A and B rows) ----
    const uint32_t xorc  = (uint32_t)(lane & 7) << 4;
    const uint32_t halfA = (uint32_t)(lane >> 4) << 4;          // k-half select for A
    const uint32_t halfB = (uint32_t)((lane >> 3) & 1) << 4;    // k-half select for B
    uint32_t aRowB[4], bRowB[4];
#pragma unroll
    for (int mt = 0; mt < 4; mt++)
        aRowB[mt] = (uint32_t)((warp_m * 64 + mt * 16 + (lane & 15)) * 128);
#pragma unroll
    for (int h = 0; h < 4; h++)                                  // 4 n16 groups = 64 cols
        bRowB[h] = (uint32_t)((warp_n * 64 + h * 16 + ((lane >> 4) << 3) + (lane & 7)) * 128) + 16384;

    // f16x2-packed accumulators: acc[mt][nt][r], r0={c0,c1}, r1={c2,c3}
    uint32_t acc[4][8][2];
#pragma unroll
    for (int m = 0; m < 4; m++)
#pragma unroll
        for (int n = 0; n < 8; n++) { acc[m][n][0] = 0u; acc[m][n][1] = 0u; }

    issue(0); CP_COMMIT();
    issue(1); CP_COMMIT();

    for (int cnt = 0; cnt < CHUNKS; cnt++) {
        if (cnt + 1 < CHUNKS) { asm volatile("cp.async.wait_group 1;"); }
        else                  { asm volatile("cp.async.wait_group 0;"); }
        __syncthreads();   // chunk `cnt` resident in stage cnt%2

        const uint32_t sS = sbase + (uint32_t)(cnt % STAGES) * STG_BYTES;
#pragma unroll
        for (int kk = 0; kk < 4; kk++) {       // k16 steps: 8 LDSM -> 32 MMA
            uint32_t a[4][4], b[8][2];
            const uint32_t colA = (uint32_t)(kk << 5) + halfA;
            const uint32_t colB = (uint32_t)(kk << 5) + halfB;
#pragma unroll
            for (int mt = 0; mt < 4; mt++)
                LDMATRIX_X4(a[mt], sS + aRowB[mt] + (colA ^ xorc));
#pragma unroll
            for (int h = 0; h < 4; h++) {
                uint32_t r4[4];
                LDMATRIX_X4(r4, sS + bRowB[h] + (colB ^ xorc));
                b[2 * h][0] = r4[0];     b[2 * h][1] = r4[1];
                b[2 * h + 1][0] = r4[2]; b[2 * h + 1][1] = r4[3];
            }
#pragma unroll
            for (int mt = 0; mt < 4; mt++)
#pragma unroll
                for (int nt = 0; nt < 8; nt++)
                    MMA_F16ACC(acc[mt][nt], a[mt], b[nt]);
        }

        // ---- per-N-tile fused epilogue (every 8th chunk) ----
        if ((cnt & 7) == 7) {
            const int ntile = cnt >> 3;
            const int colq = ntile * CTA_N + warp_n * 64 + (lane & 3) * 2;

#pragma unroll
            for (int mt = 0; mt < 4; mt++) {
#pragma unroll
                for (int half = 0; half < 2; half++) {
                    const int row = warp_m * 64 + mt * 16 + (lane >> 2) + half * 8;
                    float v1 = NEG_INF, v2 = NEG_INF; int i1 = 0, i2 = 0;
#pragma unroll
                    for (int nt = 0; nt < 8; nt++) {
                        const int c0 = colq + nt * 8;
                        const float2 p = __half22float2(
                            *reinterpret_cast<const __half2*>(&acc[mt][nt][half]));
                        const float s0 = fmaf(2.f, p.x, -__ldg(cnorm + c0));
                        const float s1 = fmaf(2.f, p.y, -__ldg(cnorm + c0 + 1));
                        if (better(s0, c0, v1, i1))      { v2 = v1; i2 = i1; v1 = s0; i1 = c0; }
                        else if (better(s0, c0, v2, i2)) { v2 = s0; i2 = c0; }
                        if (better(s1, c0 + 1, v1, i1))      { v2 = v1; i2 = i1; v1 = s1; i1 = c0 + 1; }
                        else if (better(s1, c0 + 1, v2, i2)) { v2 = s1; i2 = c0 + 1; }
                    }
                    // merge top-2 across the 4 lanes of the quad (xor 1, 2)
#pragma unroll
                    for (int off = 1; off <= 2; off <<= 1) {
                        const float u1 = __shfl_xor_sync(0xffffffffu, v1, off);
                        const int   j1 = __shfl_xor_sync(0xffffffffu, i1, off);
                        const float u2 = __shfl_xor_sync(0xffffffffu, v2, off);
                        const int   j2 = __shfl_xor_sync(0xffffffffu, i2, off);
                        if (better(u1, j1, v1, i1))      { v2 = v1; i2 = i1; v1 = u1; i1 = j1; }
                        else if (better(u1, j1, v2, i2)) { v2 = u1; i2 = j1; }
                        if (better(u2, j2, v2, i2)) {
                            if (better(u2, j2, v1, i1)) { v2 = v1; i2 = i1; v1 = u2; i1 = j2; }
                            else                         { v2 = u2; i2 = j2; }
                        }
                    }
                    if ((lane & 3) == 0) {   // quad leader updates (warp_n,row) top-3 list
                        const int base = (warp_n * 128 + row) * 3;
                        insert3(cv + base, ci + base, v1, i1);
                        insert3(cv + base, ci + base, v2, i2);
                    }
                }
            }
#pragma unroll
            for (int m = 0; m < 4; m++)
#pragma unroll
                for (int n = 0; n < 8; n++) { acc[m][n][0] = 0u; acc[m][n][1] = 0u; }
        }

        // RACE FIX (R15 bug): with 2 stages, issue(cnt+2) overwrites the stage
        // just computed (cnt%2). Barrier ensures every warp finished reading it.
        __syncthreads();
        if (cnt + 2 < CHUNKS) { issue(cnt + 2); CP_COMMIT(); }
    }

    __syncthreads();   // all cand lists visible before cross-warp merge

    // ---- merge 4 quarters x top-3 -> global top-4 candidates per query ----
    if (tid < CTA_M) {
        float bv[4] = {NEG_INF, NEG_INF, NEG_INF, NEG_INF};
        int   bi[4] = {0, 0, 0, 0};
#pragma unroll
        for (int w = 0; w < 4; w++)
#pragma unroll
            for (int e = 0; e < 3; e++) {
                const float v = cv[(w * 128 + tid) * 3 + e];
                const int  ix = ci[(w * 128 + tid) * 3 + e];
                if (better(v, ix, bv[0], bi[0])) {
                    bv[3]=bv[2]; bi[3]=bi[2]; bv[2]=bv[1]; bi[2]=bi[1];
                    bv[1]=bv[0]; bi[1]=bi[0]; bv[0]=v; bi[0]=ix;
                } else if (better(v, ix, bv[1], bi[1])) {
                    bv[3]=bv[2]; bi[3]=bi[2]; bv[2]=bv[1]; bi[2]=bi[1]; bv[1]=v; bi[1]=ix;
                } else if (better(v, ix, bv[2], bi[2])) {
                    bv[3]=bv[2]; bi[3]=bi[2]; bv[2]=v; bi[2]=ix;
                } else if (better(v, ix, bv[3], bi[3])) {
                    bv[3]=v; bi[3]=ix;
                }
            }
        cand[rowBase + tid] = make_int4(bi[0], bi[1], bi[2], bi[3]);
    }
}

// ============================ entry point ============================
extern "C" void kernel_launch(void* const* d_in, const int* in_sizes, int n_in,
                              void* d_out, int out_size) {
    const float *x, *cb;
    if (in_sizes[0] >= in_sizes[1]) { x = (const float*)d_in[0]; cb = (const float*)d_in[1]; }
    else                            { x = (const float*)d_in[1]; cb = (const float*)d_in[0]; }
    float* out = (float*)d_out;

    void *pxh, *pch, *pcn, *pcd;
    cudaGetSymbolAddress(&pxh, g_xh);
    cudaGetSymbolAddress(&pch, g_ch);
    cudaGetSymbolAddress(&pcn, g_cnorm);
    cudaGetSymbolAddress(&pcd, g_cand);

    cudaFuncSetAttribute(vq_main, cudaFuncAttributeMaxDynamicSharedMemorySize, SMEM_TOTAL);

    convert_kernel<<<(NUM_QUERY * D_DIM / 4 + 255) / 256, 256>>>(x, (__half*)pxh, NUM_QUERY * D_DIM / 4);
    convert_kernel<<<(NUM_CODES * D_DIM / 4 + 255) / 256, 256>>>(cb, (__half*)pch, NUM_CODES * D_DIM / 4);
    cnorm_kernel<<<NUM_CODES, 128>>>(cb);
    vq_main<<<NUM_QUERY / CTA_M, THREADS, SMEM_TOTAL>>>(
        (const __half*)pxh, (const __half*)pch, (const float*)pcn, (int4*)pcd);
    rescore_kernel<<<NUM_QUERY / 8, 256>>>(x, cb, (const int4*)pcd, out);
}